// round 1
// baseline (speedup 1.0000x reference)
#include <cuda_runtime.h>
#include <math.h>

// ---------------- problem constants ----------------
#define N_NODES 50000
#define N_EDGES 1000000
#define IN_DIM  256
#define HIDD    128
#define OUTD    64
#define NREL    2
#define NEG_SLOPE 0.2f

// ---------------- scratch (static device globals; no allocation) ----------------
__device__ float    g_proj1[NREL * N_NODES * HIDD];   // 51.2 MB
__device__ float    g_proj2[NREL * N_NODES * OUTD];   // 25.6 MB
__device__ float    g_h1   [N_NODES * HIDD];          // 25.6 MB
__device__ float    g_h2   [N_NODES * OUTD];          // 12.8 MB
__device__ float    g_hid  [N_NODES * HIDD];          // 25.6 MB (decoder hidden)
__device__ float    g_sq   [NREL * N_NODES];
__device__ float    g_sk   [NREL * N_NODES];
__device__ unsigned g_maxb [N_NODES];
__device__ float    g_den  [N_NODES];
__device__ float    g_w1T  [OUTD * HIDD];             // 64 x 128
__device__ float    g_w2T  [HIDD * IN_DIM];           // 128 x 256

// ordered-uint encoding for float atomicMax
__device__ __forceinline__ unsigned f2o(float f) {
    unsigned u = __float_as_uint(f);
    return (u & 0x80000000u) ? ~u : (u | 0x80000000u);
}
__device__ __forceinline__ float o2f(unsigned u) {
    return (u & 0x80000000u) ? __uint_as_float(u & 0x7fffffffu) : __uint_as_float(~u);
}
#define KEY_NEG_INF 0x007fffffu   // f2o(-inf)

__device__ __forceinline__ void red_add_v4(float* p, float4 v) {
    asm volatile("red.global.add.v4.f32 [%0], {%1,%2,%3,%4};"
                 :: "l"(p), "f"(v.x), "f"(v.y), "f"(v.z), "f"(v.w) : "memory");
}

__device__ __forceinline__ float warp_sum(float s) {
    #pragma unroll
    for (int o = 16; o > 0; o >>= 1) s += __shfl_xor_sync(0xffffffffu, s, o);
    return s;
}

// ---------------- fills ----------------
__global__ void fill_f(float* p, float v, int n) {
    int i = blockIdx.x * blockDim.x + threadIdx.x;
    if (i < n) p[i] = v;
}
__global__ void fill_u(unsigned* p, unsigned v, int n) {
    int i = blockIdx.x * blockDim.x + threadIdx.x;
    if (i < n) p[i] = v;
}

// ---------------- generic SGEMM: C[M x Nfull] (+batch z over B,C) ----------------
// TM=128, TK=8, 256 threads, micro tile 8 x (TN/16)
template <int TN>
__global__ void __launch_bounds__(256) sgemm(const float* __restrict__ A,
                                             const float* __restrict__ B,
                                             float* __restrict__ C,
                                             int M, int Nfull, int K,
                                             const float* __restrict__ bias,
                                             long strideB, long strideC) {
    constexpr int TM = 128, TK = 8, TNr = TN / 16;
    __shared__ float As[TK][TM];
    __shared__ float Bs[TK][TN];
    const int tid = threadIdx.x;
    const int tx = tid & 15, ty = tid >> 4;
    const int m0 = blockIdx.x * TM;
    const int n0 = blockIdx.y * TN;
    const float* Bp = B + (long)blockIdx.z * strideB;
    float* Cp = C + (long)blockIdx.z * strideC;

    float acc[8][TNr];
    #pragma unroll
    for (int i = 0; i < 8; i++)
        #pragma unroll
        for (int j = 0; j < TNr; j++) acc[i][j] = 0.f;

    const int arow = tid >> 1;
    const int ak   = (tid & 1) << 2;
    const bool arow_ok = (m0 + arow) < M;

    for (int k0 = 0; k0 < K; k0 += TK) {
        float4 av = make_float4(0.f, 0.f, 0.f, 0.f);
        if (arow_ok)
            av = *(const float4*)(A + (long)(m0 + arow) * K + k0 + ak);
        As[ak + 0][arow] = av.x;
        As[ak + 1][arow] = av.y;
        As[ak + 2][arow] = av.z;
        As[ak + 3][arow] = av.w;

        if constexpr (TN == 128) {
            int bk = tid >> 5, bn = (tid & 31) << 2;
            *(float4*)&Bs[bk][bn] =
                *(const float4*)(Bp + (long)(k0 + bk) * Nfull + n0 + bn);
        } else {  // TN == 64
            if (tid < 128) {
                int bk = tid >> 4, bn = (tid & 15) << 2;
                *(float4*)&Bs[bk][bn] =
                    *(const float4*)(Bp + (long)(k0 + bk) * Nfull + n0 + bn);
            }
        }
        __syncthreads();

        #pragma unroll
        for (int kk = 0; kk < TK; kk++) {
            float af[8], bf[TNr];
            *(float4*)&af[0] = *(const float4*)&As[kk][ty * 8];
            *(float4*)&af[4] = *(const float4*)&As[kk][ty * 8 + 4];
            #pragma unroll
            for (int j = 0; j < TNr; j += 4)
                *(float4*)&bf[j] = *(const float4*)&Bs[kk][tx * TNr + j];
            #pragma unroll
            for (int i = 0; i < 8; i++)
                #pragma unroll
                for (int j = 0; j < TNr; j++)
                    acc[i][j] += af[i] * bf[j];
        }
        __syncthreads();
    }

    #pragma unroll
    for (int i = 0; i < 8; i++) {
        int row = m0 + ty * 8 + i;
        if (row >= M) continue;
        #pragma unroll
        for (int j = 0; j < TNr; j += 4) {
            int col = n0 + tx * TNr + j;
            float4 v = make_float4(acc[i][j], acc[i][j + 1], acc[i][j + 2], acc[i][j + 3]);
            if (bias) {
                v.x += bias[col]; v.y += bias[col + 1];
                v.z += bias[col + 2]; v.w += bias[col + 3];
            }
            *(float4*)(Cp + (long)row * Nfull + col) = v;
        }
    }
}

// ---------------- per-row attention score dots ----------------
// rows of length 128: one warp per row, computes row.q and row.k
__global__ void rowdot128(const float* __restrict__ P, const float* __restrict__ q,
                          const float* __restrict__ k, float* __restrict__ sq,
                          float* __restrict__ sk, int rows) {
    int w = (blockIdx.x * blockDim.x + threadIdx.x) >> 5;
    int lane = threadIdx.x & 31;
    if (w >= rows) return;
    float4 pv = *(const float4*)(P + (long)w * 128 + lane * 4);
    float4 qv = ((const float4*)q)[lane];
    float4 kv = ((const float4*)k)[lane];
    float s1 = pv.x * qv.x + pv.y * qv.y + pv.z * qv.z + pv.w * qv.w;
    float s2 = pv.x * kv.x + pv.y * kv.y + pv.z * kv.z + pv.w * kv.w;
    s1 = warp_sum(s1);
    s2 = warp_sum(s2);
    if (lane == 0) { sq[w] = s1; sk[w] = s2; }
}

__global__ void rowdot64(const float* __restrict__ P, const float* __restrict__ q,
                         const float* __restrict__ k, float* __restrict__ sq,
                         float* __restrict__ sk, int rows) {
    int w = (blockIdx.x * blockDim.x + threadIdx.x) >> 5;
    int lane = threadIdx.x & 31;
    if (w >= rows) return;
    float2 pv = *(const float2*)(P + (long)w * 64 + lane * 2);
    float2 qv = ((const float2*)q)[lane];
    float2 kv = ((const float2*)k)[lane];
    float s1 = pv.x * qv.x + pv.y * qv.y;
    float s2 = pv.x * kv.x + pv.y * kv.y;
    s1 = warp_sum(s1);
    s2 = warp_sum(s2);
    if (lane == 0) { sq[w] = s1; sk[w] = s2; }
}

// ---------------- edge kernels ----------------
__global__ void edge_score(const int* __restrict__ ei, const int* __restrict__ et,
                           const float* __restrict__ sq, const float* __restrict__ sk,
                           float* __restrict__ raw, unsigned* __restrict__ nmax) {
    int e = blockIdx.x * blockDim.x + threadIdx.x;
    if (e >= N_EDGES) return;
    int s = ei[e], d = ei[N_EDGES + e], r = et[e];
    float a = sq[r * N_NODES + d] + sk[r * N_NODES + s];
    a = (a >= 0.f) ? a : NEG_SLOPE * a;
    raw[e] = a;
    atomicMax(&nmax[d], f2o(a));
}

__global__ void edge_exp(const int* __restrict__ ei, float* __restrict__ raw,
                         const unsigned* __restrict__ nmax, float* __restrict__ den) {
    int e = blockIdx.x * blockDim.x + threadIdx.x;
    if (e >= N_EDGES) return;
    int d = ei[N_EDGES + e];
    float ex = expf(raw[e] - o2f(nmax[d]));
    raw[e] = ex;
    atomicAdd(&den[d], ex);
}

// layer 1 aggregation: one warp per edge, 128-float row
__global__ void aggregate128(const int* __restrict__ ei, const int* __restrict__ et,
                             float* __restrict__ att, const float* __restrict__ den,
                             const float* __restrict__ proj, float* __restrict__ out) {
    int e = (blockIdx.x * blockDim.x + threadIdx.x) >> 5;
    int lane = threadIdx.x & 31;
    if (e >= N_EDGES) return;
    int s = ei[e], d = ei[N_EDGES + e], r = et[e];
    float w = att[e] / (den[d] + 1e-16f);
    if (lane == 0) att[e] = w;
    float4 pv = *(const float4*)(proj + ((long)r * N_NODES + s) * 128 + lane * 4);
    float4 v = make_float4(pv.x * w, pv.y * w, pv.z * w, pv.w * w);
    red_add_v4(out + (long)d * 128 + lane * 4, v);
}

// layer 2 aggregation: half-warp per edge (64 floats), 2 edges per warp
__global__ void aggregate64(const int* __restrict__ ei, const int* __restrict__ et,
                            float* __restrict__ att, const float* __restrict__ den,
                            const float* __restrict__ proj, float* __restrict__ out) {
    int gw = (blockIdx.x * blockDim.x + threadIdx.x) >> 5;
    int lane = threadIdx.x & 31;
    int e = gw * 2 + (lane >> 4);
    int l16 = lane & 15;
    if (e >= N_EDGES) return;
    int s = ei[e], d = ei[N_EDGES + e], r = et[e];
    float w = att[e] / (den[d] + 1e-16f);
    if (l16 == 0) att[e] = w;
    float4 pv = *(const float4*)(proj + ((long)r * N_NODES + s) * 64 + l16 * 4);
    float4 v = make_float4(pv.x * w, pv.y * w, pv.z * w, pv.w * w);
    red_add_v4(out + (long)d * 64 + l16 * 4, v);
}

// ---------------- elementwise ----------------
__global__ void elu_inplace(float* p, int n) {
    int i = blockIdx.x * blockDim.x + threadIdx.x;
    if (i < n) {
        float x = p[i];
        p[i] = (x > 0.f) ? x : expm1f(x);
    }
}
__global__ void elu_store(const float* __restrict__ src, float* __restrict__ dst, int n) {
    int i = blockIdx.x * blockDim.x + threadIdx.x;
    if (i < n) {
        float x = src[i];
        dst[i] = (x > 0.f) ? x : expm1f(x);
    }
}

// transpose: dst[c*Rr + r] = src[r*Cc + c]   (src: Rr x Cc)
__global__ void transpose_k(const float* __restrict__ src, float* __restrict__ dst,
                            int Rr, int Cc) {
    int i = blockIdx.x * blockDim.x + threadIdx.x;
    if (i >= Rr * Cc) return;
    int r = i / Cc, c = i % Cc;
    dst[c * Rr + r] = src[i];
}

// ---------------- launch ----------------
extern "C" void kernel_launch(void* const* d_in, const int* in_sizes, int n_in,
                              void* d_out, int out_size) {
    const float* features = (const float*)d_in[0];
    const int*   ei       = (const int*)d_in[1];
    const int*   et       = (const int*)d_in[2];
    const float* W1  = (const float*)d_in[3];
    const float* q1  = (const float*)d_in[4];
    const float* k1  = (const float*)d_in[5];
    const float* W2  = (const float*)d_in[6];
    const float* q2  = (const float*)d_in[7];
    const float* k2  = (const float*)d_in[8];
    const float* dw1 = (const float*)d_in[9];
    const float* db1 = (const float*)d_in[10];
    const float* dw2 = (const float*)d_in[11];
    const float* db2 = (const float*)d_in[12];

    float* out  = (float*)d_out;
    float* h2o  = out;                                  // N x 64
    float* h3o  = out + (long)N_NODES * OUTD;           // N x 256
    float* att1 = h3o + (long)N_NODES * IN_DIM;         // E
    float* att2 = att1 + N_EDGES;                       // E

    float *proj1, *proj2, *h1, *h2, *hid, *sq, *sk, *den, *w1T, *w2T;
    unsigned* maxb;
    cudaGetSymbolAddress((void**)&proj1, g_proj1);
    cudaGetSymbolAddress((void**)&proj2, g_proj2);
    cudaGetSymbolAddress((void**)&h1, g_h1);
    cudaGetSymbolAddress((void**)&h2, g_h2);
    cudaGetSymbolAddress((void**)&hid, g_hid);
    cudaGetSymbolAddress((void**)&sq, g_sq);
    cudaGetSymbolAddress((void**)&sk, g_sk);
    cudaGetSymbolAddress((void**)&maxb, g_maxb);
    cudaGetSymbolAddress((void**)&den, g_den);
    cudaGetSymbolAddress((void**)&w1T, g_w1T);
    cudaGetSymbolAddress((void**)&w2T, g_w2T);

    const int TB = 256;
    auto cdiv = [](long a, long b) { return (int)((a + b - 1) / b); };
    dim3 gM(cdiv(N_NODES, 128));

    // ---- layer 1 ----
    fill_f<<<cdiv(N_NODES * HIDD, TB), TB>>>(h1, 0.f, N_NODES * HIDD);
    fill_u<<<cdiv(N_NODES, TB), TB>>>(maxb, KEY_NEG_INF, N_NODES);
    fill_f<<<cdiv(N_NODES, TB), TB>>>(den, 0.f, N_NODES);

    sgemm<128><<<dim3(gM.x, 1, NREL), 256>>>(features, W1, proj1,
        N_NODES, HIDD, IN_DIM, nullptr, (long)IN_DIM * HIDD, (long)N_NODES * HIDD);
    rowdot128<<<cdiv((long)NREL * N_NODES * 32, TB), TB>>>(proj1, q1, k1, sq, sk,
                                                           NREL * N_NODES);
    edge_score<<<cdiv(N_EDGES, TB), TB>>>(ei, et, sq, sk, att1, maxb);
    edge_exp<<<cdiv(N_EDGES, TB), TB>>>(ei, att1, maxb, den);
    aggregate128<<<cdiv((long)N_EDGES * 32, TB), TB>>>(ei, et, att1, den, proj1, h1);
    elu_inplace<<<cdiv(N_NODES * HIDD, TB), TB>>>(h1, N_NODES * HIDD);

    // ---- layer 2 ----
    fill_f<<<cdiv(N_NODES * OUTD, TB), TB>>>(h2, 0.f, N_NODES * OUTD);
    fill_u<<<cdiv(N_NODES, TB), TB>>>(maxb, KEY_NEG_INF, N_NODES);
    fill_f<<<cdiv(N_NODES, TB), TB>>>(den, 0.f, N_NODES);

    sgemm<64><<<dim3(gM.x, 1, NREL), 256>>>(h1, W2, proj2,
        N_NODES, OUTD, HIDD, nullptr, (long)HIDD * OUTD, (long)N_NODES * OUTD);
    rowdot64<<<cdiv((long)NREL * N_NODES * 32, TB), TB>>>(proj2, q2, k2, sq, sk,
                                                          NREL * N_NODES);
    edge_score<<<cdiv(N_EDGES, TB), TB>>>(ei, et, sq, sk, att2, maxb);
    edge_exp<<<cdiv(N_EDGES, TB), TB>>>(ei, att2, maxb, den);
    aggregate64<<<cdiv((long)N_EDGES * 16, TB), TB>>>(ei, et, att2, den, proj2, h2);
    elu_store<<<cdiv(N_NODES * OUTD, TB), TB>>>(h2, h2o, N_NODES * OUTD);

    // ---- decoder ----
    transpose_k<<<cdiv(HIDD * OUTD, TB), TB>>>(dw1, w1T, HIDD, OUTD);   // -> 64 x 128
    transpose_k<<<cdiv(IN_DIM * HIDD, TB), TB>>>(dw2, w2T, IN_DIM, HIDD); // -> 128 x 256
    sgemm<128><<<dim3(gM.x, 1, 1), 256>>>(h2o, w1T, hid,
        N_NODES, HIDD, OUTD, db1, 0, 0);
    sgemm<128><<<dim3(gM.x, 2, 1), 256>>>(hid, w2T, h3o,
        N_NODES, IN_DIM, HIDD, db2, 0, 0);
}

// round 2
// speedup vs baseline: 1.5058x; 1.5058x over previous
#include <cuda_runtime.h>
#include <math.h>
#include <stdint.h>

// ---------------- problem constants ----------------
#define N_NODES 50000
#define N_EDGES 1000000
#define IN_DIM  256
#define HIDD    128
#define OUTD    64
#define NREL    2
#define NEG_SLOPE 0.2f

// ---------------- scratch (static device globals; no allocation) ----------------
__device__ float    g_proj1[NREL * N_NODES * HIDD];   // 51.2 MB
__device__ float    g_proj2[NREL * N_NODES * OUTD];   // 25.6 MB
__device__ float    g_h1   [N_NODES * HIDD];          // 25.6 MB
__device__ float    g_h2   [N_NODES * OUTD];          // 12.8 MB
__device__ float    g_hid  [N_NODES * HIDD];          // 25.6 MB (decoder hidden)
__device__ float    g_sq   [NREL * N_NODES];
__device__ float    g_sk   [NREL * N_NODES];
__device__ unsigned g_maxb [N_NODES];
__device__ float    g_den  [N_NODES];
__device__ float    g_w1T  [OUTD * HIDD];             // 64 x 128
__device__ float    g_w2T  [HIDD * IN_DIM];           // 128 x 256

// ordered-uint encoding for float atomicMax
__device__ __forceinline__ unsigned f2o(float f) {
    unsigned u = __float_as_uint(f);
    return (u & 0x80000000u) ? ~u : (u | 0x80000000u);
}
__device__ __forceinline__ float o2f(unsigned u) {
    return (u & 0x80000000u) ? __uint_as_float(u & 0x7fffffffu) : __uint_as_float(~u);
}
#define KEY_NEG_INF 0x007fffffu   // f2o(-inf)

__device__ __forceinline__ void red_add_v4(float* p, float4 v) {
    asm volatile("red.global.add.v4.f32 [%0], {%1,%2,%3,%4};"
                 :: "l"(p), "f"(v.x), "f"(v.y), "f"(v.z), "f"(v.w) : "memory");
}

__device__ __forceinline__ float warp_sum(float s) {
    #pragma unroll
    for (int o = 16; o > 0; o >>= 1) s += __shfl_xor_sync(0xffffffffu, s, o);
    return s;
}

__device__ __forceinline__ uint32_t f2tf(float f) {
    uint32_t u;
    asm("cvt.rna.tf32.f32 %0, %1;" : "=r"(u) : "f"(f));
    return u;
}

__device__ __forceinline__ void cp_async16(uint32_t sdst, const void* gsrc, int nbytes) {
    asm volatile("cp.async.cg.shared.global [%0], [%1], 16, %2;\n"
                 :: "r"(sdst), "l"(gsrc), "r"(nbytes));
}

// ---------------- fills ----------------
__global__ void fill_f(float* p, float v, int n) {
    int i = blockIdx.x * blockDim.x + threadIdx.x;
    if (i < n) p[i] = v;
}
__global__ void fill_u(unsigned* p, unsigned v, int n) {
    int i = blockIdx.x * blockDim.x + threadIdx.x;
    if (i < n) p[i] = v;
}

// ---------------- TF32 tensor-core GEMM ----------------
// C[M x Nfull] = A[M x K] @ B[K x Nfull] (+ optional bias over cols),
// batch z over B,C. BM=128, BK=16, 256 threads (8 warps), warp tile 32 x (BN/2).
// mma.sync.aligned.m16n8k8.row.col.f32.tf32.tf32.f32
template <int BN>
__global__ void __launch_bounds__(256)
gemm_tf32(const float* __restrict__ A, const float* __restrict__ B,
          float* __restrict__ C, int M, int Nfull, int K,
          const float* __restrict__ bias, long strideB, long strideC) {
    constexpr int BM = 128, BK = 16;
    constexpr int AST = BK + 4;   // 20 floats: conflict-free for A frag pattern
    constexpr int BST = BN + 8;   // conflict-free for B frag pattern
    constexpr int WN = BN / 2;    // 2 warps in N
    constexpr int NT = WN / 8;    // n-tiles per warp
    constexpr int B_TPR = BN / 4;          // threads per B row (float4 units)
    constexpr int B_RPR = 256 / B_TPR;     // B rows per round
    constexpr int B_ROUNDS = BK / B_RPR;   // rounds to load B tile

    __shared__ __align__(16) float As[2][BM * AST];
    __shared__ __align__(16) float Bs[2][BK * BST];

    const int tid  = threadIdx.x;
    const int lane = tid & 31;
    const int warp = tid >> 5;
    const int gid  = lane >> 2;    // 0..7
    const int tig  = lane & 3;     // 0..3
    const int wm   = warp & 3;     // 4 warps in M
    const int wn   = warp >> 2;    // 2 warps in N

    const int m0 = blockIdx.x * BM;
    const int n0 = blockIdx.y * BN;
    const float* Bp = B + (long)blockIdx.z * strideB;
    float* Cp = C + (long)blockIdx.z * strideC;

    // loader indices
    const int a_row = tid >> 2;          // 0..63 (2 rounds of 64 rows)
    const int a_cg  = (tid & 3) * 4;     // col group (floats)
    const int b_row = tid / B_TPR;
    const int b_cg  = (tid % B_TPR) * 4;

    float c[2][NT][4];
    #pragma unroll
    for (int mt = 0; mt < 2; mt++)
        #pragma unroll
        for (int nt = 0; nt < NT; nt++)
            #pragma unroll
            for (int i = 0; i < 4; i++) c[mt][nt][i] = 0.f;

    uint32_t asb = (uint32_t)__cvta_generic_to_shared(&As[0][0]);
    uint32_t bsb = (uint32_t)__cvta_generic_to_shared(&Bs[0][0]);

    auto prefetch = [&](int k0, int buf) {
        // A tile: BM x BK, 2 rounds of 64 rows
        #pragma unroll
        for (int r = 0; r < 2; r++) {
            int row = r * 64 + a_row;
            int nb = (m0 + row < M) ? 16 : 0;
            uint32_t dst = asb + (uint32_t)buf * (BM * AST * 4) +
                           (uint32_t)(row * AST + a_cg) * 4;
            cp_async16(dst, A + (long)(m0 + row) * K + k0 + a_cg, nb);
        }
        // B tile: BK x BN
        #pragma unroll
        for (int r = 0; r < B_ROUNDS; r++) {
            int row = r * B_RPR + b_row;
            uint32_t dst = bsb + (uint32_t)buf * (BK * BST * 4) +
                           (uint32_t)(row * BST + b_cg) * 4;
            cp_async16(dst, Bp + (long)(k0 + row) * Nfull + n0 + b_cg, 16);
        }
        asm volatile("cp.async.commit_group;");
    };

    const int iters = K / BK;
    prefetch(0, 0);

    for (int it = 0; it < iters; it++) {
        if (it + 1 < iters) {
            prefetch((it + 1) * BK, (it + 1) & 1);
            asm volatile("cp.async.wait_group 1;");
        } else {
            asm volatile("cp.async.wait_group 0;");
        }
        __syncthreads();

        const float* as = As[it & 1];
        const float* bs = Bs[it & 1];

        #pragma unroll
        for (int ks = 0; ks < BK; ks += 8) {
            uint32_t a[2][4], b[NT][2];
            #pragma unroll
            for (int mt = 0; mt < 2; mt++) {
                int r0 = wm * 32 + mt * 16 + gid;
                a[mt][0] = f2tf(as[r0 * AST + ks + tig]);
                a[mt][1] = f2tf(as[(r0 + 8) * AST + ks + tig]);
                a[mt][2] = f2tf(as[r0 * AST + ks + tig + 4]);
                a[mt][3] = f2tf(as[(r0 + 8) * AST + ks + tig + 4]);
            }
            #pragma unroll
            for (int nt = 0; nt < NT; nt++) {
                int cb = wn * WN + nt * 8 + gid;
                b[nt][0] = f2tf(bs[(ks + tig) * BST + cb]);
                b[nt][1] = f2tf(bs[(ks + tig + 4) * BST + cb]);
            }
            #pragma unroll
            for (int mt = 0; mt < 2; mt++)
                #pragma unroll
                for (int nt = 0; nt < NT; nt++) {
                    asm volatile(
                        "mma.sync.aligned.m16n8k8.row.col.f32.tf32.tf32.f32 "
                        "{%0,%1,%2,%3}, {%4,%5,%6,%7}, {%8,%9}, {%0,%1,%2,%3};"
                        : "+f"(c[mt][nt][0]), "+f"(c[mt][nt][1]),
                          "+f"(c[mt][nt][2]), "+f"(c[mt][nt][3])
                        : "r"(a[mt][0]), "r"(a[mt][1]), "r"(a[mt][2]), "r"(a[mt][3]),
                          "r"(b[nt][0]), "r"(b[nt][1]));
                }
        }
        __syncthreads();
    }

    // epilogue
    #pragma unroll
    for (int mt = 0; mt < 2; mt++) {
        int r0 = m0 + wm * 32 + mt * 16 + gid;
        #pragma unroll
        for (int nt = 0; nt < NT; nt++) {
            int col = n0 + wn * WN + nt * 8 + 2 * tig;
            float bx = 0.f, by = 0.f;
            if (bias) { bx = bias[col]; by = bias[col + 1]; }
            if (r0 < M) {
                float2 v = make_float2(c[mt][nt][0] + bx, c[mt][nt][1] + by);
                *(float2*)(Cp + (long)r0 * Nfull + col) = v;
            }
            if (r0 + 8 < M) {
                float2 v = make_float2(c[mt][nt][2] + bx, c[mt][nt][3] + by);
                *(float2*)(Cp + (long)(r0 + 8) * Nfull + col) = v;
            }
        }
    }
}

// ---------------- per-row attention score dots ----------------
__global__ void rowdot128(const float* __restrict__ P, const float* __restrict__ q,
                          const float* __restrict__ k, float* __restrict__ sq,
                          float* __restrict__ sk, int rows) {
    int w = (blockIdx.x * blockDim.x + threadIdx.x) >> 5;
    int lane = threadIdx.x & 31;
    if (w >= rows) return;
    float4 pv = *(const float4*)(P + (long)w * 128 + lane * 4);
    float4 qv = ((const float4*)q)[lane];
    float4 kv = ((const float4*)k)[lane];
    float s1 = pv.x * qv.x + pv.y * qv.y + pv.z * qv.z + pv.w * qv.w;
    float s2 = pv.x * kv.x + pv.y * kv.y + pv.z * kv.z + pv.w * kv.w;
    s1 = warp_sum(s1);
    s2 = warp_sum(s2);
    if (lane == 0) { sq[w] = s1; sk[w] = s2; }
}

__global__ void rowdot64(const float* __restrict__ P, const float* __restrict__ q,
                         const float* __restrict__ k, float* __restrict__ sq,
                         float* __restrict__ sk, int rows) {
    int w = (blockIdx.x * blockDim.x + threadIdx.x) >> 5;
    int lane = threadIdx.x & 31;
    if (w >= rows) return;
    float2 pv = *(const float2*)(P + (long)w * 64 + lane * 2);
    float2 qv = ((const float2*)q)[lane];
    float2 kv = ((const float2*)k)[lane];
    float s1 = pv.x * qv.x + pv.y * qv.y;
    float s2 = pv.x * kv.x + pv.y * kv.y;
    s1 = warp_sum(s1);
    s2 = warp_sum(s2);
    if (lane == 0) { sq[w] = s1; sk[w] = s2; }
}

// ---------------- edge kernels ----------------
__global__ void edge_score(const int* __restrict__ ei, const int* __restrict__ et,
                           const float* __restrict__ sq, const float* __restrict__ sk,
                           float* __restrict__ raw, unsigned* __restrict__ nmax) {
    int e = blockIdx.x * blockDim.x + threadIdx.x;
    if (e >= N_EDGES) return;
    int s = ei[e], d = ei[N_EDGES + e], r = et[e];
    float a = sq[r * N_NODES + d] + sk[r * N_NODES + s];
    a = (a >= 0.f) ? a : NEG_SLOPE * a;
    raw[e] = a;
    atomicMax(&nmax[d], f2o(a));
}

__global__ void edge_exp(const int* __restrict__ ei, float* __restrict__ raw,
                         const unsigned* __restrict__ nmax, float* __restrict__ den) {
    int e = blockIdx.x * blockDim.x + threadIdx.x;
    if (e >= N_EDGES) return;
    int d = ei[N_EDGES + e];
    float ex = expf(raw[e] - o2f(nmax[d]));
    raw[e] = ex;
    atomicAdd(&den[d], ex);
}

// layer 1 aggregation: one warp per edge, 128-float row
__global__ void aggregate128(const int* __restrict__ ei, const int* __restrict__ et,
                             float* __restrict__ att, const float* __restrict__ den,
                             const float* __restrict__ proj, float* __restrict__ out) {
    int e = (blockIdx.x * blockDim.x + threadIdx.x) >> 5;
    int lane = threadIdx.x & 31;
    if (e >= N_EDGES) return;
    int s = ei[e], d = ei[N_EDGES + e], r = et[e];
    float w = att[e] / (den[d] + 1e-16f);
    if (lane == 0) att[e] = w;
    float4 pv = *(const float4*)(proj + ((long)r * N_NODES + s) * 128 + lane * 4);
    float4 v = make_float4(pv.x * w, pv.y * w, pv.z * w, pv.w * w);
    red_add_v4(out + (long)d * 128 + lane * 4, v);
}

// layer 2 aggregation: half-warp per edge (64 floats)
__global__ void aggregate64(const int* __restrict__ ei, const int* __restrict__ et,
                            float* __restrict__ att, const float* __restrict__ den,
                            const float* __restrict__ proj, float* __restrict__ out) {
    int gw = (blockIdx.x * blockDim.x + threadIdx.x) >> 5;
    int lane = threadIdx.x & 31;
    int e = gw * 2 + (lane >> 4);
    int l16 = lane & 15;
    if (e >= N_EDGES) return;
    int s = ei[e], d = ei[N_EDGES + e], r = et[e];
    float w = att[e] / (den[d] + 1e-16f);
    if (l16 == 0) att[e] = w;
    float4 pv = *(const float4*)(proj + ((long)r * N_NODES + s) * 64 + l16 * 4);
    float4 v = make_float4(pv.x * w, pv.y * w, pv.z * w, pv.w * w);
    red_add_v4(out + (long)d * 64 + l16 * 4, v);
}

// ---------------- elementwise ----------------
__global__ void elu_inplace(float* p, int n) {
    int i = blockIdx.x * blockDim.x + threadIdx.x;
    if (i < n) {
        float x = p[i];
        p[i] = (x > 0.f) ? x : expm1f(x);
    }
}
__global__ void elu_store(const float* __restrict__ src, float* __restrict__ dst, int n) {
    int i = blockIdx.x * blockDim.x + threadIdx.x;
    if (i < n) {
        float x = src[i];
        dst[i] = (x > 0.f) ? x : expm1f(x);
    }
}

// transpose: dst[c*Rr + r] = src[r*Cc + c]   (src: Rr x Cc)
__global__ void transpose_k(const float* __restrict__ src, float* __restrict__ dst,
                            int Rr, int Cc) {
    int i = blockIdx.x * blockDim.x + threadIdx.x;
    if (i >= Rr * Cc) return;
    int r = i / Cc, c = i % Cc;
    dst[c * Rr + r] = src[i];
}

// ---------------- launch ----------------
extern "C" void kernel_launch(void* const* d_in, const int* in_sizes, int n_in,
                              void* d_out, int out_size) {
    const float* features = (const float*)d_in[0];
    const int*   ei       = (const int*)d_in[1];
    const int*   et       = (const int*)d_in[2];
    const float* W1  = (const float*)d_in[3];
    const float* q1  = (const float*)d_in[4];
    const float* k1  = (const float*)d_in[5];
    const float* W2  = (const float*)d_in[6];
    const float* q2  = (const float*)d_in[7];
    const float* k2  = (const float*)d_in[8];
    const float* dw1 = (const float*)d_in[9];
    const float* db1 = (const float*)d_in[10];
    const float* dw2 = (const float*)d_in[11];
    const float* db2 = (const float*)d_in[12];

    float* out  = (float*)d_out;
    float* h2o  = out;                                  // N x 64
    float* h3o  = out + (long)N_NODES * OUTD;           // N x 256
    float* att1 = h3o + (long)N_NODES * IN_DIM;         // E
    float* att2 = att1 + N_EDGES;                       // E

    float *proj1, *proj2, *h1, *h2, *hid, *sq, *sk, *den, *w1T, *w2T;
    unsigned* maxb;
    cudaGetSymbolAddress((void**)&proj1, g_proj1);
    cudaGetSymbolAddress((void**)&proj2, g_proj2);
    cudaGetSymbolAddress((void**)&h1, g_h1);
    cudaGetSymbolAddress((void**)&h2, g_h2);
    cudaGetSymbolAddress((void**)&hid, g_hid);
    cudaGetSymbolAddress((void**)&sq, g_sq);
    cudaGetSymbolAddress((void**)&sk, g_sk);
    cudaGetSymbolAddress((void**)&maxb, g_maxb);
    cudaGetSymbolAddress((void**)&den, g_den);
    cudaGetSymbolAddress((void**)&w1T, g_w1T);
    cudaGetSymbolAddress((void**)&w2T, g_w2T);

    const int TB = 256;
    auto cdiv = [](long a, long b) { return (int)((a + b - 1) / b); };
    const int gM = cdiv(N_NODES, 128);

    // ---- layer 1 ----
    fill_f<<<cdiv(N_NODES * HIDD, TB), TB>>>(h1, 0.f, N_NODES * HIDD);
    fill_u<<<cdiv(N_NODES, TB), TB>>>(maxb, KEY_NEG_INF, N_NODES);
    fill_f<<<cdiv(N_NODES, TB), TB>>>(den, 0.f, N_NODES);

    gemm_tf32<128><<<dim3(gM, 1, NREL), 256>>>(features, W1, proj1,
        N_NODES, HIDD, IN_DIM, nullptr, (long)IN_DIM * HIDD, (long)N_NODES * HIDD);
    rowdot128<<<cdiv((long)NREL * N_NODES * 32, TB), TB>>>(proj1, q1, k1, sq, sk,
                                                           NREL * N_NODES);
    edge_score<<<cdiv(N_EDGES, TB), TB>>>(ei, et, sq, sk, att1, maxb);
    edge_exp<<<cdiv(N_EDGES, TB), TB>>>(ei, att1, maxb, den);
    aggregate128<<<cdiv((long)N_EDGES * 32, TB), TB>>>(ei, et, att1, den, proj1, h1);
    elu_inplace<<<cdiv(N_NODES * HIDD, TB), TB>>>(h1, N_NODES * HIDD);

    // ---- layer 2 ----
    fill_f<<<cdiv(N_NODES * OUTD, TB), TB>>>(h2, 0.f, N_NODES * OUTD);
    fill_u<<<cdiv(N_NODES, TB), TB>>>(maxb, KEY_NEG_INF, N_NODES);
    fill_f<<<cdiv(N_NODES, TB), TB>>>(den, 0.f, N_NODES);

    gemm_tf32<64><<<dim3(gM, 1, NREL), 256>>>(h1, W2, proj2,
        N_NODES, OUTD, HIDD, nullptr, (long)HIDD * OUTD, (long)N_NODES * OUTD);
    rowdot64<<<cdiv((long)NREL * N_NODES * 32, TB), TB>>>(proj2, q2, k2, sq, sk,
                                                          NREL * N_NODES);
    edge_score<<<cdiv(N_EDGES, TB), TB>>>(ei, et, sq, sk, att2, maxb);
    edge_exp<<<cdiv(N_EDGES, TB), TB>>>(ei, att2, maxb, den);
    aggregate64<<<cdiv((long)N_EDGES * 16, TB), TB>>>(ei, et, att2, den, proj2, h2);
    elu_store<<<cdiv(N_NODES * OUTD, TB), TB>>>(h2, h2o, N_NODES * OUTD);

    // ---- decoder ----
    transpose_k<<<cdiv(HIDD * OUTD, TB), TB>>>(dw1, w1T, HIDD, OUTD);     // -> 64 x 128
    transpose_k<<<cdiv(IN_DIM * HIDD, TB), TB>>>(dw2, w2T, IN_DIM, HIDD); // -> 128 x 256
    gemm_tf32<128><<<dim3(gM, 1, 1), 256>>>(h2o, w1T, hid,
        N_NODES, HIDD, OUTD, db1, 0, 0);
    gemm_tf32<128><<<dim3(gM, 2, 1), 256>>>(hid, w2T, h3o,
        N_NODES, IN_DIM, HIDD, db2, 0, 0);
}

// round 3
// speedup vs baseline: 1.6243x; 1.0787x over previous
#include <cuda_runtime.h>
#include <math.h>
#include <stdint.h>

// ---------------- problem constants ----------------
#define N_NODES 50000
#define N_EDGES 1000000
#define IN_DIM  256
#define HIDD    128
#define OUTD    64
#define NREL    2
#define NEG_SLOPE 0.2f

// ---------------- scratch (static device globals; no allocation) ----------------
__device__ float    g_proj1[NREL * N_NODES * HIDD];   // 51.2 MB
__device__ float    g_proj2[NREL * N_NODES * OUTD];   // 25.6 MB
__device__ float    g_h1   [N_NODES * HIDD];          // 25.6 MB
__device__ float    g_hid  [N_NODES * HIDD];          // 25.6 MB (decoder hidden)
__device__ float    g_sq   [NREL * N_NODES];
__device__ float    g_sk   [NREL * N_NODES];
__device__ float    g_w1T  [OUTD * HIDD];             // 64 x 128
__device__ float    g_w2T  [HIDD * IN_DIM];           // 128 x 256
// CSR over destination nodes
__device__ int      g_off  [N_NODES + 1];
__device__ int      g_cur  [N_NODES];                 // counts, then cursors
__device__ int      g_eid  [N_EDGES];
__device__ int      g_pack [N_EDGES];                 // src | (rel << 20)
__device__ int      g_bsum [256];

__device__ __forceinline__ float warp_sum(float s) {
    #pragma unroll
    for (int o = 16; o > 0; o >>= 1) s += __shfl_xor_sync(0xffffffffu, s, o);
    return s;
}
__device__ __forceinline__ float warp_max(float s) {
    #pragma unroll
    for (int o = 16; o > 0; o >>= 1) s = fmaxf(s, __shfl_xor_sync(0xffffffffu, s, o));
    return s;
}

__device__ __forceinline__ uint32_t f2tf(float f) {
    uint32_t u;
    asm("cvt.rna.tf32.f32 %0, %1;" : "=r"(u) : "f"(f));
    return u;
}

__device__ __forceinline__ void cp_async16(uint32_t sdst, const void* gsrc, int nbytes) {
    asm volatile("cp.async.cg.shared.global [%0], [%1], 16, %2;\n"
                 :: "r"(sdst), "l"(gsrc), "r"(nbytes));
}

// ---------------- fills ----------------
__global__ void fill_i(int* p, int v, int n) {
    int i = blockIdx.x * blockDim.x + threadIdx.x;
    if (i < n) p[i] = v;
}

// ---------------- CSR build ----------------
__global__ void hist_k(const int* __restrict__ ei, int* __restrict__ cnt) {
    int e = blockIdx.x * blockDim.x + threadIdx.x;
    if (e < N_EDGES) atomicAdd(&cnt[ei[N_EDGES + e]], 1);
}

// per-block exclusive scan of 256 counts; block totals to bsum
__global__ void scan_local(const int* __restrict__ cnt, int* __restrict__ off,
                           int* __restrict__ bsum) {
    __shared__ int sh[256];
    int i = blockIdx.x * 256 + threadIdx.x;
    int v = (i < N_NODES) ? cnt[i] : 0;
    sh[threadIdx.x] = v;
    __syncthreads();
    #pragma unroll
    for (int o = 1; o < 256; o <<= 1) {
        int t = (threadIdx.x >= o) ? sh[threadIdx.x - o] : 0;
        __syncthreads();
        sh[threadIdx.x] += t;
        __syncthreads();
    }
    if (i < N_NODES) off[i] = sh[threadIdx.x] - v;   // exclusive
    if (threadIdx.x == 255) bsum[blockIdx.x] = sh[255];
}

__global__ void scan_bsum(int* __restrict__ bsum, int nb) {
    __shared__ int sh[256];
    int v = (threadIdx.x < nb) ? bsum[threadIdx.x] : 0;
    sh[threadIdx.x] = v;
    __syncthreads();
    #pragma unroll
    for (int o = 1; o < 256; o <<= 1) {
        int t = (threadIdx.x >= o) ? sh[threadIdx.x - o] : 0;
        __syncthreads();
        sh[threadIdx.x] += t;
        __syncthreads();
    }
    if (threadIdx.x < nb) bsum[threadIdx.x] = sh[threadIdx.x] - v;  // exclusive
}

__global__ void add_base(int* __restrict__ off, const int* __restrict__ bsum,
                         int* __restrict__ cur) {
    int i = blockIdx.x * blockDim.x + threadIdx.x;
    if (i < N_NODES) {
        int v = off[i] + bsum[i >> 8];
        off[i] = v;
        cur[i] = v;
    }
    if (i == 0) off[N_NODES] = N_EDGES;
}

__global__ void scatter_k(const int* __restrict__ ei, const int* __restrict__ et,
                          int* __restrict__ cur, int* __restrict__ eid,
                          int* __restrict__ pack) {
    int e = blockIdx.x * blockDim.x + threadIdx.x;
    if (e >= N_EDGES) return;
    int d = ei[N_EDGES + e];
    int pos = atomicAdd(&cur[d], 1);
    eid[pos] = e;
    pack[pos] = ei[e] | (et[e] << 20);
}

// ---------------- TF32 tensor-core GEMM ----------------
template <int BN>
__global__ void __launch_bounds__(256)
gemm_tf32(const float* __restrict__ A, const float* __restrict__ B,
          float* __restrict__ C, int M, int Nfull, int K,
          const float* __restrict__ bias, long strideB, long strideC) {
    constexpr int BM = 128, BK = 16;
    constexpr int AST = BK + 4;
    constexpr int BST = BN + 8;
    constexpr int WN = BN / 2;
    constexpr int NT = WN / 8;
    constexpr int B_TPR = BN / 4;
    constexpr int B_RPR = 256 / B_TPR;
    constexpr int B_ROUNDS = BK / B_RPR;

    __shared__ __align__(16) float As[2][BM * AST];
    __shared__ __align__(16) float Bs[2][BK * BST];

    const int tid  = threadIdx.x;
    const int lane = tid & 31;
    const int warp = tid >> 5;
    const int gid  = lane >> 2;
    const int tig  = lane & 3;
    const int wm   = warp & 3;
    const int wn   = warp >> 2;

    const int m0 = blockIdx.x * BM;
    const int n0 = blockIdx.y * BN;
    const float* Bp = B + (long)blockIdx.z * strideB;
    float* Cp = C + (long)blockIdx.z * strideC;

    const int a_row = tid >> 2;
    const int a_cg  = (tid & 3) * 4;
    const int b_row = tid / B_TPR;
    const int b_cg  = (tid % B_TPR) * 4;

    float c[2][NT][4];
    #pragma unroll
    for (int mt = 0; mt < 2; mt++)
        #pragma unroll
        for (int nt = 0; nt < NT; nt++)
            #pragma unroll
            for (int i = 0; i < 4; i++) c[mt][nt][i] = 0.f;

    uint32_t asb = (uint32_t)__cvta_generic_to_shared(&As[0][0]);
    uint32_t bsb = (uint32_t)__cvta_generic_to_shared(&Bs[0][0]);

    auto prefetch = [&](int k0, int buf) {
        #pragma unroll
        for (int r = 0; r < 2; r++) {
            int row = r * 64 + a_row;
            int nb = (m0 + row < M) ? 16 : 0;
            uint32_t dst = asb + (uint32_t)buf * (BM * AST * 4) +
                           (uint32_t)(row * AST + a_cg) * 4;
            cp_async16(dst, A + (long)(m0 + row) * K + k0 + a_cg, nb);
        }
        #pragma unroll
        for (int r = 0; r < B_ROUNDS; r++) {
            int row = r * B_RPR + b_row;
            uint32_t dst = bsb + (uint32_t)buf * (BK * BST * 4) +
                           (uint32_t)(row * BST + b_cg) * 4;
            cp_async16(dst, Bp + (long)(k0 + row) * Nfull + n0 + b_cg, 16);
        }
        asm volatile("cp.async.commit_group;");
    };

    const int iters = K / BK;
    prefetch(0, 0);

    for (int it = 0; it < iters; it++) {
        if (it + 1 < iters) {
            prefetch((it + 1) * BK, (it + 1) & 1);
            asm volatile("cp.async.wait_group 1;");
        } else {
            asm volatile("cp.async.wait_group 0;");
        }
        __syncthreads();

        const float* as = As[it & 1];
        const float* bs = Bs[it & 1];

        #pragma unroll
        for (int ks = 0; ks < BK; ks += 8) {
            uint32_t a[2][4], b[NT][2];
            #pragma unroll
            for (int mt = 0; mt < 2; mt++) {
                int r0 = wm * 32 + mt * 16 + gid;
                a[mt][0] = f2tf(as[r0 * AST + ks + tig]);
                a[mt][1] = f2tf(as[(r0 + 8) * AST + ks + tig]);
                a[mt][2] = f2tf(as[r0 * AST + ks + tig + 4]);
                a[mt][3] = f2tf(as[(r0 + 8) * AST + ks + tig + 4]);
            }
            #pragma unroll
            for (int nt = 0; nt < NT; nt++) {
                int cb = wn * WN + nt * 8 + gid;
                b[nt][0] = f2tf(bs[(ks + tig) * BST + cb]);
                b[nt][1] = f2tf(bs[(ks + tig + 4) * BST + cb]);
            }
            #pragma unroll
            for (int mt = 0; mt < 2; mt++)
                #pragma unroll
                for (int nt = 0; nt < NT; nt++) {
                    asm volatile(
                        "mma.sync.aligned.m16n8k8.row.col.f32.tf32.tf32.f32 "
                        "{%0,%1,%2,%3}, {%4,%5,%6,%7}, {%8,%9}, {%0,%1,%2,%3};"
                        : "+f"(c[mt][nt][0]), "+f"(c[mt][nt][1]),
                          "+f"(c[mt][nt][2]), "+f"(c[mt][nt][3])
                        : "r"(a[mt][0]), "r"(a[mt][1]), "r"(a[mt][2]), "r"(a[mt][3]),
                          "r"(b[nt][0]), "r"(b[nt][1]));
                }
        }
        __syncthreads();
    }

    #pragma unroll
    for (int mt = 0; mt < 2; mt++) {
        int r0 = m0 + wm * 32 + mt * 16 + gid;
        #pragma unroll
        for (int nt = 0; nt < NT; nt++) {
            int col = n0 + wn * WN + nt * 8 + 2 * tig;
            float bx = 0.f, by = 0.f;
            if (bias) { bx = bias[col]; by = bias[col + 1]; }
            if (r0 < M) {
                float2 v = make_float2(c[mt][nt][0] + bx, c[mt][nt][1] + by);
                *(float2*)(Cp + (long)r0 * Nfull + col) = v;
            }
            if (r0 + 8 < M) {
                float2 v = make_float2(c[mt][nt][2] + bx, c[mt][nt][3] + by);
                *(float2*)(Cp + (long)(r0 + 8) * Nfull + col) = v;
            }
        }
    }
}

// ---------------- per-row attention score dots ----------------
__global__ void rowdot128(const float* __restrict__ P, const float* __restrict__ q,
                          const float* __restrict__ k, float* __restrict__ sq,
                          float* __restrict__ sk, int rows) {
    int w = (blockIdx.x * blockDim.x + threadIdx.x) >> 5;
    int lane = threadIdx.x & 31;
    if (w >= rows) return;
    float4 pv = *(const float4*)(P + (long)w * 128 + lane * 4);
    float4 qv = ((const float4*)q)[lane];
    float4 kv = ((const float4*)k)[lane];
    float s1 = pv.x * qv.x + pv.y * qv.y + pv.z * qv.z + pv.w * qv.w;
    float s2 = pv.x * kv.x + pv.y * kv.y + pv.z * kv.z + pv.w * kv.w;
    s1 = warp_sum(s1);
    s2 = warp_sum(s2);
    if (lane == 0) { sq[w] = s1; sk[w] = s2; }
}

__global__ void rowdot64(const float* __restrict__ P, const float* __restrict__ q,
                         const float* __restrict__ k, float* __restrict__ sq,
                         float* __restrict__ sk, int rows) {
    int w = (blockIdx.x * blockDim.x + threadIdx.x) >> 5;
    int lane = threadIdx.x & 31;
    if (w >= rows) return;
    float2 pv = *(const float2*)(P + (long)w * 64 + lane * 2);
    float2 qv = ((const float2*)q)[lane];
    float2 kv = ((const float2*)k)[lane];
    float s1 = pv.x * qv.x + pv.y * qv.y;
    float s2 = pv.x * kv.x + pv.y * kv.y;
    s1 = warp_sum(s1);
    s2 = warp_sum(s2);
    if (lane == 0) { sq[w] = s1; sk[w] = s2; }
}

// ---------------- fused softmax + aggregation + ELU, one warp per dst node ----
template <int O>   // O = 128 or 64
__global__ void __launch_bounds__(256)
attn_agg(const int* __restrict__ off, const int* __restrict__ eidA,
         const int* __restrict__ packA, const float* __restrict__ sq,
         const float* __restrict__ sk, const float* __restrict__ proj,
         float* __restrict__ att, float* __restrict__ outp) {
    constexpr int F = O / 32;   // floats per lane
    int node = (blockIdx.x * blockDim.x + threadIdx.x) >> 5;
    int lane = threadIdx.x & 31;
    if (node >= N_NODES) return;
    const int beg = off[node], deg = off[node + 1] - off[node];

    float acc[F];
    #pragma unroll
    for (int i = 0; i < F; i++) acc[i] = 0.f;

    if (deg > 0) {
        auto score = [&](int p) {
            int s = p & 0xFFFFF, r = p >> 20;
            float a = sq[r * N_NODES + node] + sk[r * N_NODES + s];
            return (a >= 0.f) ? a : NEG_SLOPE * a;
        };

        // first chunk cached in registers (deg <= 32 is the common case)
        int p0 = 0; float a0 = -INFINITY;
        if (lane < deg) { p0 = packA[beg + lane]; a0 = score(p0); }

        float lm = a0;
        for (int base = 32; base < deg; base += 32) {
            int i = base + lane;
            if (i < deg) lm = fmaxf(lm, score(packA[beg + i]));
        }
        const float m = warp_max(lm);

        float e0 = (lane < deg) ? expf(a0 - m) : 0.f;
        float ls = e0;
        for (int base = 32; base < deg; base += 32) {
            int i = base + lane;
            if (i < deg) ls += expf(score(packA[beg + i]) - m);
        }
        const float inv = 1.f / (warp_sum(ls) + 1e-16f);

        for (int base = 0; base < deg; base += 32) {
            int i = base + lane;
            float ex; int p;
            if (base == 0) { ex = e0; p = p0; }
            else if (i < deg) { p = packA[beg + i]; ex = expf(score(p) - m); }
            else { p = 0; ex = 0.f; }
            if (i < deg) att[eidA[beg + i]] = ex * inv;
            int cnt = min(32, deg - base);
            for (int j = 0; j < cnt; j++) {
                float w = __shfl_sync(0xffffffffu, ex, j) * inv;
                int pj  = __shfl_sync(0xffffffffu, p, j);
                int sj = pj & 0xFFFFF, rj = pj >> 20;
                const float* row = proj + ((long)rj * N_NODES + sj) * O;
                if constexpr (F == 4) {
                    float4 pv = ((const float4*)row)[lane];
                    acc[0] += w * pv.x; acc[1] += w * pv.y;
                    acc[2] += w * pv.z; acc[3] += w * pv.w;
                } else {
                    float2 pv = ((const float2*)row)[lane];
                    acc[0] += w * pv.x; acc[1] += w * pv.y;
                }
            }
        }
    }

    // ELU + coalesced write
    #pragma unroll
    for (int i = 0; i < F; i++) acc[i] = (acc[i] > 0.f) ? acc[i] : expm1f(acc[i]);
    if constexpr (F == 4) {
        float4 v = make_float4(acc[0], acc[1], acc[2], acc[3]);
        *(float4*)(outp + (long)node * 128 + lane * 4) = v;
    } else {
        float2 v = make_float2(acc[0], acc[1]);
        *(float2*)(outp + (long)node * 64 + lane * 2) = v;
    }
}

// transpose: dst[c*Rr + r] = src[r*Cc + c]   (src: Rr x Cc)
__global__ void transpose_k(const float* __restrict__ src, float* __restrict__ dst,
                            int Rr, int Cc) {
    int i = blockIdx.x * blockDim.x + threadIdx.x;
    if (i >= Rr * Cc) return;
    int r = i / Cc, c = i % Cc;
    dst[c * Rr + r] = src[i];
}

// ---------------- launch ----------------
extern "C" void kernel_launch(void* const* d_in, const int* in_sizes, int n_in,
                              void* d_out, int out_size) {
    const float* features = (const float*)d_in[0];
    const int*   ei       = (const int*)d_in[1];
    const int*   et       = (const int*)d_in[2];
    const float* W1  = (const float*)d_in[3];
    const float* q1  = (const float*)d_in[4];
    const float* k1  = (const float*)d_in[5];
    const float* W2  = (const float*)d_in[6];
    const float* q2  = (const float*)d_in[7];
    const float* k2  = (const float*)d_in[8];
    const float* dw1 = (const float*)d_in[9];
    const float* db1 = (const float*)d_in[10];
    const float* dw2 = (const float*)d_in[11];
    const float* db2 = (const float*)d_in[12];

    float* out  = (float*)d_out;
    float* h2o  = out;                                  // N x 64
    float* h3o  = out + (long)N_NODES * OUTD;           // N x 256
    float* att1 = h3o + (long)N_NODES * IN_DIM;         // E
    float* att2 = att1 + N_EDGES;                       // E

    float *proj1, *proj2, *h1, *hid, *sq, *sk, *w1T, *w2T;
    int *off, *cur, *eid, *pack, *bsum;
    cudaGetSymbolAddress((void**)&proj1, g_proj1);
    cudaGetSymbolAddress((void**)&proj2, g_proj2);
    cudaGetSymbolAddress((void**)&h1, g_h1);
    cudaGetSymbolAddress((void**)&hid, g_hid);
    cudaGetSymbolAddress((void**)&sq, g_sq);
    cudaGetSymbolAddress((void**)&sk, g_sk);
    cudaGetSymbolAddress((void**)&w1T, g_w1T);
    cudaGetSymbolAddress((void**)&w2T, g_w2T);
    cudaGetSymbolAddress((void**)&off, g_off);
    cudaGetSymbolAddress((void**)&cur, g_cur);
    cudaGetSymbolAddress((void**)&eid, g_eid);
    cudaGetSymbolAddress((void**)&pack, g_pack);
    cudaGetSymbolAddress((void**)&bsum, g_bsum);

    const int TB = 256;
    auto cdiv = [](long a, long b) { return (int)((a + b - 1) / b); };
    const int gM = cdiv(N_NODES, 128);
    const int nb = cdiv(N_NODES, 256);   // 196

    // ---- CSR build (once, shared by both layers) ----
    fill_i<<<cdiv(N_NODES, TB), TB>>>(cur, 0, N_NODES);
    hist_k<<<cdiv(N_EDGES, TB), TB>>>(ei, cur);
    scan_local<<<nb, 256>>>(cur, off, bsum);
    scan_bsum<<<1, 256>>>(bsum, nb);
    add_base<<<cdiv(N_NODES, TB), TB>>>(off, bsum, cur);
    scatter_k<<<cdiv(N_EDGES, TB), TB>>>(ei, et, cur, eid, pack);

    // ---- layer 1 ----
    gemm_tf32<128><<<dim3(gM, 1, NREL), 256>>>(features, W1, proj1,
        N_NODES, HIDD, IN_DIM, nullptr, (long)IN_DIM * HIDD, (long)N_NODES * HIDD);
    rowdot128<<<cdiv((long)NREL * N_NODES * 32, TB), TB>>>(proj1, q1, k1, sq, sk,
                                                           NREL * N_NODES);
    attn_agg<128><<<cdiv((long)N_NODES * 32, TB), TB>>>(off, eid, pack, sq, sk,
                                                        proj1, att1, h1);

    // ---- layer 2 ----
    gemm_tf32<64><<<dim3(gM, 1, NREL), 256>>>(h1, W2, proj2,
        N_NODES, OUTD, HIDD, nullptr, (long)HIDD * OUTD, (long)N_NODES * OUTD);
    rowdot64<<<cdiv((long)NREL * N_NODES * 32, TB), TB>>>(proj2, q2, k2, sq, sk,
                                                          NREL * N_NODES);
    attn_agg<64><<<cdiv((long)N_NODES * 32, TB), TB>>>(off, eid, pack, sq, sk,
                                                       proj2, att2, h2o);

    // ---- decoder ----
    transpose_k<<<cdiv(HIDD * OUTD, TB), TB>>>(dw1, w1T, HIDD, OUTD);     // -> 64 x 128
    transpose_k<<<cdiv(IN_DIM * HIDD, TB), TB>>>(dw2, w2T, IN_DIM, HIDD); // -> 128 x 256
    gemm_tf32<128><<<dim3(gM, 1, 1), 256>>>(h2o, w1T, hid,
        N_NODES, HIDD, OUTD, db1, 0, 0);
    gemm_tf32<128><<<dim3(gM, 2, 1), 256>>>(hid, w2T, h3o,
        N_NODES, IN_DIM, HIDD, db2, 0, 0);
}

// round 5
// speedup vs baseline: 2.1322x; 1.3127x over previous
#include <cuda_runtime.h>
#include <math.h>
#include <stdint.h>

// ---------------- problem constants ----------------
#define N_NODES 50000
#define N_EDGES 1000000
#define IN_DIM  256
#define HIDD    128
#define OUTD    64
#define NREL    2
#define NEG_SLOPE 0.2f

// ---------------- scratch (static device globals; no allocation) ----------------
__device__ float    g_proj1[NREL * N_NODES * HIDD];   // 51.2 MB
__device__ float    g_proj2[NREL * N_NODES * OUTD];   // 25.6 MB
__device__ float    g_h1   [N_NODES * HIDD];          // 25.6 MB
__device__ float    g_hid  [N_NODES * HIDD];          // 25.6 MB (decoder hidden)
__device__ float    g_sq   [NREL * N_NODES];
__device__ float    g_sk   [NREL * N_NODES];
__device__ float    g_w1T  [OUTD * HIDD];             // 64 x 128
__device__ float    g_w2T  [HIDD * IN_DIM];           // 128 x 256
// CSR over destination nodes
__device__ int      g_off  [N_NODES + 1];
__device__ int      g_cur  [N_NODES];                 // counts, then cursors
__device__ int      g_eid  [N_EDGES];
__device__ int      g_pack [N_EDGES];                 // src | (rel << 20)
__device__ int      g_bsum [256];

__device__ __forceinline__ float warp_sum(float s) {
    #pragma unroll
    for (int o = 16; o > 0; o >>= 1) s += __shfl_xor_sync(0xffffffffu, s, o);
    return s;
}
__device__ __forceinline__ float warp_max(float s) {
    #pragma unroll
    for (int o = 16; o > 0; o >>= 1) s = fmaxf(s, __shfl_xor_sync(0xffffffffu, s, o));
    return s;
}

__device__ __forceinline__ float f2tf_f(float f) {
    uint32_t u;
    asm("cvt.rna.tf32.f32 %0, %1;" : "=r"(u) : "f"(f));
    return __uint_as_float(u);
}

__device__ __forceinline__ void cp_async16(uint32_t sdst, const void* gsrc, int nbytes) {
    asm volatile("cp.async.cg.shared.global [%0], [%1], 16, %2;\n"
                 :: "r"(sdst), "l"(gsrc), "r"(nbytes));
}

// ---------------- fills ----------------
__global__ void fill_i(int* p, int v, int n) {
    int i = blockIdx.x * blockDim.x + threadIdx.x;
    if (i < n) p[i] = v;
}
__global__ void fill2_f(float* a, float* b, int n) {
    int i = blockIdx.x * blockDim.x + threadIdx.x;
    if (i < n) { a[i] = 0.f; b[i] = 0.f; }
}

// ---------------- CSR build ----------------
__global__ void hist_k(const int* __restrict__ ei, int* __restrict__ cnt) {
    int e = blockIdx.x * blockDim.x + threadIdx.x;
    if (e < N_EDGES) atomicAdd(&cnt[ei[N_EDGES + e]], 1);
}

__global__ void scan_local(const int* __restrict__ cnt, int* __restrict__ off,
                           int* __restrict__ bsum) {
    __shared__ int sh[256];
    int i = blockIdx.x * 256 + threadIdx.x;
    int v = (i < N_NODES) ? cnt[i] : 0;
    sh[threadIdx.x] = v;
    __syncthreads();
    #pragma unroll
    for (int o = 1; o < 256; o <<= 1) {
        int t = (threadIdx.x >= o) ? sh[threadIdx.x - o] : 0;
        __syncthreads();
        sh[threadIdx.x] += t;
        __syncthreads();
    }
    if (i < N_NODES) off[i] = sh[threadIdx.x] - v;   // exclusive
    if (threadIdx.x == 255) bsum[blockIdx.x] = sh[255];
}

__global__ void scan_bsum(int* __restrict__ bsum, int nb) {
    __shared__ int sh[256];
    int v = (threadIdx.x < nb) ? bsum[threadIdx.x] : 0;
    sh[threadIdx.x] = v;
    __syncthreads();
    #pragma unroll
    for (int o = 1; o < 256; o <<= 1) {
        int t = (threadIdx.x >= o) ? sh[threadIdx.x - o] : 0;
        __syncthreads();
        sh[threadIdx.x] += t;
        __syncthreads();
    }
    if (threadIdx.x < nb) bsum[threadIdx.x] = sh[threadIdx.x] - v;  // exclusive
}

__global__ void add_base(int* __restrict__ off, const int* __restrict__ bsum,
                         int* __restrict__ cur) {
    int i = blockIdx.x * blockDim.x + threadIdx.x;
    if (i < N_NODES) {
        int v = off[i] + bsum[i >> 8];
        off[i] = v;
        cur[i] = v;
    }
    if (i == 0) off[N_NODES] = N_EDGES;
}

__global__ void scatter_k(const int* __restrict__ ei, const int* __restrict__ et,
                          int* __restrict__ cur, int* __restrict__ eid,
                          int* __restrict__ pack) {
    int e = blockIdx.x * blockDim.x + threadIdx.x;
    if (e >= N_EDGES) return;
    int d = ei[N_EDGES + e];
    int pos = atomicAdd(&cur[d], 1);
    eid[pos] = e;
    pack[pos] = ei[e] | (et[e] << 20);
}

// ---------------- TF32 tensor-core GEMM ----------------
// C[M x Nfull] = A @ B (+ bias), batch z over B,C. Tiles converted to TF32
// in smem once per iteration (no per-fragment cvt). Optional fused q/k row
// dots accumulated atomically into sq/sk (requires grid.y==1, Nfull==BN).
template <int BN>
__global__ void __launch_bounds__(256)
gemm_tf32(const float* __restrict__ A, const float* __restrict__ B,
          float* __restrict__ C, int M, int Nfull, int K,
          const float* __restrict__ bias, long strideB, long strideC,
          const float* __restrict__ qv, const float* __restrict__ kv,
          float* __restrict__ sqo, float* __restrict__ sko) {
    constexpr int BM = 128, BK = 16;
    constexpr int AST = BK + 4;   // 20
    constexpr int BST = BN + 8;
    constexpr int WN = BN / 2;
    constexpr int NT = WN / 8;
    constexpr int B_TPR = BN / 4;
    constexpr int B_RPR = 256 / B_TPR;
    constexpr int B_ROUNDS = BK / B_RPR;

    __shared__ __align__(16) float As[2][BM * AST];
    __shared__ __align__(16) float Bs[2][BK * BST];

    const int tid  = threadIdx.x;
    const int lane = tid & 31;
    const int warp = tid >> 5;
    const int gid  = lane >> 2;
    const int tig  = lane & 3;
    const int wm   = warp & 3;
    const int wn   = warp >> 2;

    const int m0 = blockIdx.x * BM;
    const int n0 = blockIdx.y * BN;
    const float* Bp = B + (long)blockIdx.z * strideB;
    float* Cp = C + (long)blockIdx.z * strideC;

    const int a_row = tid >> 2;
    const int a_cg  = (tid & 3) * 4;
    const int b_row = tid / B_TPR;
    const int b_cg  = (tid % B_TPR) * 4;

    float c[2][NT][4];
    #pragma unroll
    for (int mt = 0; mt < 2; mt++)
        #pragma unroll
        for (int nt = 0; nt < NT; nt++)
            #pragma unroll
            for (int i = 0; i < 4; i++) c[mt][nt][i] = 0.f;

    uint32_t asb = (uint32_t)__cvta_generic_to_shared(&As[0][0]);
    uint32_t bsb = (uint32_t)__cvta_generic_to_shared(&Bs[0][0]);

    auto prefetch = [&](int k0, int buf) {
        #pragma unroll
        for (int r = 0; r < 2; r++) {
            int row = r * 64 + a_row;
            int nb = (m0 + row < M) ? 16 : 0;
            uint32_t dst = asb + (uint32_t)buf * (BM * AST * 4) +
                           (uint32_t)(row * AST + a_cg) * 4;
            cp_async16(dst, A + (long)(m0 + row) * K + k0 + a_cg, nb);
        }
        #pragma unroll
        for (int r = 0; r < B_ROUNDS; r++) {
            int row = r * B_RPR + b_row;
            uint32_t dst = bsb + (uint32_t)buf * (BK * BST * 4) +
                           (uint32_t)(row * BST + b_cg) * 4;
            cp_async16(dst, Bp + (long)(k0 + row) * Nfull + n0 + b_cg, 16);
        }
        asm volatile("cp.async.commit_group;");
    };

    const int iters = K / BK;
    prefetch(0, 0);

    // in-place tf32 conversion indices
    const int car = tid >> 1;             // A row 0..127
    const int cac = (tid & 1) * 8;        // A col 0 or 8
    const int cbr = tid >> 4;             // B row 0..15
    const int cbc = (tid & 15) * (BN / 16);  // 8 (BN=128) or 4 (BN=64) cols

    for (int it = 0; it < iters; it++) {
        if (it + 1 < iters) {
            prefetch((it + 1) * BK, (it + 1) & 1);
            asm volatile("cp.async.wait_group 1;");
        } else {
            asm volatile("cp.async.wait_group 0;");
        }
        __syncthreads();

        // convert this buffer's tiles to tf32 in place (vectorized)
        {
            float* aw = As[it & 1];
            float* bw = Bs[it & 1];
            float4* pa = (float4*)&aw[car * AST + cac];
            float4 v0 = pa[0], v1 = pa[1];
            v0.x = f2tf_f(v0.x); v0.y = f2tf_f(v0.y);
            v0.z = f2tf_f(v0.z); v0.w = f2tf_f(v0.w);
            v1.x = f2tf_f(v1.x); v1.y = f2tf_f(v1.y);
            v1.z = f2tf_f(v1.z); v1.w = f2tf_f(v1.w);
            pa[0] = v0; pa[1] = v1;
            float4* pb = (float4*)&bw[cbr * BST + cbc];
            float4 w0 = pb[0];
            w0.x = f2tf_f(w0.x); w0.y = f2tf_f(w0.y);
            w0.z = f2tf_f(w0.z); w0.w = f2tf_f(w0.w);
            pb[0] = w0;
            if constexpr (BN == 128) {
                float4 w1 = pb[1];
                w1.x = f2tf_f(w1.x); w1.y = f2tf_f(w1.y);
                w1.z = f2tf_f(w1.z); w1.w = f2tf_f(w1.w);
                pb[1] = w1;
            }
        }
        __syncthreads();

        const uint32_t* as = (const uint32_t*)As[it & 1];
        const uint32_t* bs = (const uint32_t*)Bs[it & 1];

        #pragma unroll
        for (int ks = 0; ks < BK; ks += 8) {
            uint32_t a[2][4], b[NT][2];
            #pragma unroll
            for (int mt = 0; mt < 2; mt++) {
                int r0 = wm * 32 + mt * 16 + gid;
                a[mt][0] = as[r0 * AST + ks + tig];
                a[mt][1] = as[(r0 + 8) * AST + ks + tig];
                a[mt][2] = as[r0 * AST + ks + tig + 4];
                a[mt][3] = as[(r0 + 8) * AST + ks + tig + 4];
            }
            #pragma unroll
            for (int nt = 0; nt < NT; nt++) {
                int cb = wn * WN + nt * 8 + gid;
                b[nt][0] = bs[(ks + tig) * BST + cb];
                b[nt][1] = bs[(ks + tig + 4) * BST + cb];
            }
            #pragma unroll
            for (int mt = 0; mt < 2; mt++)
                #pragma unroll
                for (int nt = 0; nt < NT; nt++) {
                    asm volatile(
                        "mma.sync.aligned.m16n8k8.row.col.f32.tf32.tf32.f32 "
                        "{%0,%1,%2,%3}, {%4,%5,%6,%7}, {%8,%9}, {%0,%1,%2,%3};"
                        : "+f"(c[mt][nt][0]), "+f"(c[mt][nt][1]),
                          "+f"(c[mt][nt][2]), "+f"(c[mt][nt][3])
                        : "r"(a[mt][0]), "r"(a[mt][1]), "r"(a[mt][2]), "r"(a[mt][3]),
                          "r"(b[nt][0]), "r"(b[nt][1]));
                }
        }
        __syncthreads();
    }

    // epilogue: store C (+bias) and optionally fused q/k dots
    #pragma unroll
    for (int mt = 0; mt < 2; mt++) {
        int r0 = m0 + wm * 32 + mt * 16 + gid;
        #pragma unroll
        for (int nt = 0; nt < NT; nt++) {
            int col = n0 + wn * WN + nt * 8 + 2 * tig;
            float bx = 0.f, by = 0.f;
            if (bias) { bx = bias[col]; by = bias[col + 1]; }
            if (r0 < M) {
                float2 v = make_float2(c[mt][nt][0] + bx, c[mt][nt][1] + by);
                *(float2*)(Cp + (long)r0 * Nfull + col) = v;
            }
            if (r0 + 8 < M) {
                float2 v = make_float2(c[mt][nt][2] + bx, c[mt][nt][3] + by);
                *(float2*)(Cp + (long)(r0 + 8) * Nfull + col) = v;
            }
        }
    }

    if (qv) {
        long base = (long)blockIdx.z * M;
        #pragma unroll
        for (int mt = 0; mt < 2; mt++) {
            float dq0 = 0.f, dk0 = 0.f, dq1 = 0.f, dk1 = 0.f;
            #pragma unroll
            for (int nt = 0; nt < NT; nt++) {
                int col = wn * WN + nt * 8 + 2 * tig;
                float q0 = qv[col], q1 = qv[col + 1];
                float k0 = kv[col], k1 = kv[col + 1];
                dq0 += c[mt][nt][0] * q0 + c[mt][nt][1] * q1;
                dk0 += c[mt][nt][0] * k0 + c[mt][nt][1] * k1;
                dq1 += c[mt][nt][2] * q0 + c[mt][nt][3] * q1;
                dk1 += c[mt][nt][2] * k0 + c[mt][nt][3] * k1;
            }
            #pragma unroll
            for (int o = 1; o <= 2; o <<= 1) {
                dq0 += __shfl_xor_sync(0xffffffffu, dq0, o);
                dk0 += __shfl_xor_sync(0xffffffffu, dk0, o);
                dq1 += __shfl_xor_sync(0xffffffffu, dq1, o);
                dk1 += __shfl_xor_sync(0xffffffffu, dk1, o);
            }
            if (tig == 0) {
                int r0 = m0 + wm * 32 + mt * 16 + gid;
                if (r0 < M) {
                    atomicAdd(&sqo[base + r0], dq0);
                    atomicAdd(&sko[base + r0], dk0);
                }
                if (r0 + 8 < M) {
                    atomicAdd(&sqo[base + r0 + 8], dq1);
                    atomicAdd(&sko[base + r0 + 8], dk1);
                }
            }
        }
    }
}

// ---------------- fused softmax + aggregation + ELU, one warp per dst node ----
template <int O>   // O = 128 or 64
__global__ void __launch_bounds__(256)
attn_agg(const int* __restrict__ off, const int* __restrict__ eidA,
         const int* __restrict__ packA, const float* __restrict__ sq,
         const float* __restrict__ sk, const float* __restrict__ proj,
         float* __restrict__ att, float* __restrict__ outp) {
    constexpr int F = O / 32;   // floats per lane
    int node = (blockIdx.x * blockDim.x + threadIdx.x) >> 5;
    int lane = threadIdx.x & 31;
    if (node >= N_NODES) return;
    const int beg = off[node], deg = off[node + 1] - off[node];

    float acc[F];
    #pragma unroll
    for (int i = 0; i < F; i++) acc[i] = 0.f;

    if (deg > 0) {
        auto score = [&](int p) {
            int s = p & 0xFFFFF, r = p >> 20;
            float a = sq[r * N_NODES + node] + sk[r * N_NODES + s];
            return (a >= 0.f) ? a : NEG_SLOPE * a;
        };

        int p0 = 0; float a0 = -INFINITY;
        if (lane < deg) { p0 = packA[beg + lane]; a0 = score(p0); }

        float lm = a0;
        for (int base = 32; base < deg; base += 32) {
            int i = base + lane;
            if (i < deg) lm = fmaxf(lm, score(packA[beg + i]));
        }
        const float m = warp_max(lm);

        float e0 = (lane < deg) ? expf(a0 - m) : 0.f;
        float ls = e0;
        for (int base = 32; base < deg; base += 32) {
            int i = base + lane;
            if (i < deg) ls += expf(score(packA[beg + i]) - m);
        }
        const float inv = 1.f / (warp_sum(ls) + 1e-16f);

        for (int base = 0; base < deg; base += 32) {
            int i = base + lane;
            float ex; int p;
            if (base == 0) { ex = e0; p = p0; }
            else if (i < deg) { p = packA[beg + i]; ex = expf(score(p) - m); }
            else { p = 0; ex = 0.f; }
            if (i < deg) att[eidA[beg + i]] = ex * inv;
            int cnt = min(32, deg - base);
            for (int j = 0; j < cnt; j++) {
                float w = __shfl_sync(0xffffffffu, ex, j) * inv;
                int pj  = __shfl_sync(0xffffffffu, p, j);
                int sj = pj & 0xFFFFF, rj = pj >> 20;
                const float* row = proj + ((long)rj * N_NODES + sj) * O;
                if constexpr (F == 4) {
                    float4 pv = ((const float4*)row)[lane];
                    acc[0] += w * pv.x; acc[1] += w * pv.y;
                    acc[2] += w * pv.z; acc[3] += w * pv.w;
                } else {
                    float2 pv = ((const float2*)row)[lane];
                    acc[0] += w * pv.x; acc[1] += w * pv.y;
                }
            }
        }
    }

    #pragma unroll
    for (int i = 0; i < F; i++) acc[i] = (acc[i] > 0.f) ? acc[i] : expm1f(acc[i]);
    if constexpr (F == 4) {
        float4 v = make_float4(acc[0], acc[1], acc[2], acc[3]);
        *(float4*)(outp + (long)node * 128 + lane * 4) = v;
    } else {
        float2 v = make_float2(acc[0], acc[1]);
        *(float2*)(outp + (long)node * 64 + lane * 2) = v;
    }
}

// transpose: dst[c*Rr + r] = src[r*Cc + c]   (src: Rr x Cc)
__global__ void transpose_k(const float* __restrict__ src, float* __restrict__ dst,
                            int Rr, int Cc) {
    int i = blockIdx.x * blockDim.x + threadIdx.x;
    if (i >= Rr * Cc) return;
    int r = i / Cc, c = i % Cc;
    dst[c * Rr + r] = src[i];
}

// ---------------- launch ----------------
extern "C" void kernel_launch(void* const* d_in, const int* in_sizes, int n_in,
                              void* d_out, int out_size) {
    const float* features = (const float*)d_in[0];
    const int*   ei       = (const int*)d_in[1];
    const int*   et       = (const int*)d_in[2];
    const float* W1  = (const float*)d_in[3];
    const float* q1  = (const float*)d_in[4];
    const float* k1  = (const float*)d_in[5];
    const float* W2  = (const float*)d_in[6];
    const float* q2  = (const float*)d_in[7];
    const float* k2  = (const float*)d_in[8];
    const float* dw1 = (const float*)d_in[9];
    const float* db1 = (const float*)d_in[10];
    const float* dw2 = (const float*)d_in[11];
    const float* db2 = (const float*)d_in[12];

    float* out  = (float*)d_out;
    float* h2o  = out;                                  // N x 64
    float* h3o  = out + (long)N_NODES * OUTD;           // N x 256
    float* att1 = h3o + (long)N_NODES * IN_DIM;         // E
    float* att2 = att1 + N_EDGES;                       // E

    float *proj1, *proj2, *h1, *hid, *sq, *sk, *w1T, *w2T;
    int *off, *cur, *eid, *pack, *bsum;
    cudaGetSymbolAddress((void**)&proj1, g_proj1);
    cudaGetSymbolAddress((void**)&proj2, g_proj2);
    cudaGetSymbolAddress((void**)&h1, g_h1);
    cudaGetSymbolAddress((void**)&hid, g_hid);
    cudaGetSymbolAddress((void**)&sq, g_sq);
    cudaGetSymbolAddress((void**)&sk, g_sk);
    cudaGetSymbolAddress((void**)&w1T, g_w1T);
    cudaGetSymbolAddress((void**)&w2T, g_w2T);
    cudaGetSymbolAddress((void**)&off, g_off);
    cudaGetSymbolAddress((void**)&cur, g_cur);
    cudaGetSymbolAddress((void**)&eid, g_eid);
    cudaGetSymbolAddress((void**)&pack, g_pack);
    cudaGetSymbolAddress((void**)&bsum, g_bsum);

    const int TB = 256;
    auto cdiv = [](long a, long b) { return (int)((a + b - 1) / b); };
    const int gM = cdiv(N_NODES, 128);
    const int nb = cdiv(N_NODES, 256);   // 196

    // ---- CSR build (once, shared by both layers) ----
    fill_i<<<cdiv(N_NODES, TB), TB>>>(cur, 0, N_NODES);
    hist_k<<<cdiv(N_EDGES, TB), TB>>>(ei, cur);
    scan_local<<<nb, 256>>>(cur, off, bsum);
    scan_bsum<<<1, 256>>>(bsum, nb);
    add_base<<<cdiv(N_NODES, TB), TB>>>(off, bsum, cur);
    scatter_k<<<cdiv(N_EDGES, TB), TB>>>(ei, et, cur, eid, pack);

    // ---- layer 1 ----
    fill2_f<<<cdiv(NREL * N_NODES, TB), TB>>>(sq, sk, NREL * N_NODES);
    gemm_tf32<128><<<dim3(gM, 1, NREL), 256>>>(features, W1, proj1,
        N_NODES, HIDD, IN_DIM, nullptr, (long)IN_DIM * HIDD, (long)N_NODES * HIDD,
        q1, k1, sq, sk);
    attn_agg<128><<<cdiv((long)N_NODES * 32, TB), TB>>>(off, eid, pack, sq, sk,
                                                        proj1, att1, h1);

    // ---- layer 2 ----
    fill2_f<<<cdiv(NREL * N_NODES, TB), TB>>>(sq, sk, NREL * N_NODES);
    gemm_tf32<64><<<dim3(gM, 1, NREL), 256>>>(h1, W2, proj2,
        N_NODES, OUTD, HIDD, nullptr, (long)HIDD * OUTD, (long)N_NODES * OUTD,
        q2, k2, sq, sk);
    attn_agg<64><<<cdiv((long)N_NODES * 32, TB), TB>>>(off, eid, pack, sq, sk,
                                                       proj2, att2, h2o);

    // ---- decoder ----
    transpose_k<<<cdiv(HIDD * OUTD, TB), TB>>>(dw1, w1T, HIDD, OUTD);     // -> 64 x 128
    transpose_k<<<cdiv(IN_DIM * HIDD, TB), TB>>>(dw2, w2T, IN_DIM, HIDD); // -> 128 x 256
    gemm_tf32<128><<<dim3(gM, 1, 1), 256>>>(h2o, w1T, hid,
        N_NODES, HIDD, OUTD, db1, 0, 0, nullptr, nullptr, nullptr, nullptr);
    gemm_tf32<128><<<dim3(gM, 2, 1), 256>>>(hid, w2T, h3o,
        N_NODES, IN_DIM, HIDD, db2, 0, 0, nullptr, nullptr, nullptr, nullptr);
}